// round 5
// baseline (speedup 1.0000x reference)
#include <cuda_runtime.h>
#include <cuda_bf16.h>
#include <math.h>

// ---------------- problem constants ----------------
#define BATCH   4
#define LSEQ    1024
#define NMELS   80
#define DMODEL  512
#define NLAYER  6
#define DSTATE  16
#define DINNER  1024
#define DTRANK  32
#define DCONV   4
#define NROWS   (BATCH * LSEQ)          // 4096

// ---------------- scratch (static device memory; no allocation) ----------------
__device__ float g_h   [NROWS * DMODEL];
__device__ float g_xn  [NROWS * DMODEL];
__device__ float g_xr  [NROWS * 2 * DINNER];
__device__ float g_u   [NROWS * DINNER];
__device__ float g_xdbl[NROWS * 64];
__device__ float g_delta[NROWS * DINNER];
__device__ float g_y   [NROWS * DINNER];

// =====================================================================
// Big NT SGEMM: C[m,n] = sum_k A[m,k] * W[n,k]
// 128x128 tile, k-block 8, 256 threads, 8x8 microtile, LDS.128 fragments,
// double-buffered smem. Requires M%128==0, N%128==0, K%8==0.
// epilogue: v = acc (+bias[n]) (+addsrc[m*ldc+n]); act==1 -> softplus
// =====================================================================
__global__ __launch_bounds__(256)
void gemm_nt_big(const float* __restrict__ A, int lda,
                 const float* __restrict__ W, int ldw,
                 float* __restrict__ C, int ldc,
                 int K,
                 const float* __restrict__ bias,
                 const float* __restrict__ addsrc,
                 int act)
{
    __shared__ float As[2][8][132];   // k-major, padded (132%4==0 keeps 16B align)
    __shared__ float Bs[2][8][132];

    const int tid  = threadIdx.x;
    const int r0   = blockIdx.y * 128;
    const int n0   = blockIdx.x * 128;
    const int lrow = tid >> 1;            // 0..127
    const int lk4  = (tid & 1) * 4;       // 0 or 4

    const float* Ap = A + (size_t)(r0 + lrow) * lda + lk4;
    const float* Wp = W + (size_t)(n0 + lrow) * ldw + lk4;

    const int ty8 = (tid >> 4) * 8;       // row offset in tile
    const int tx8 = (tid & 15) * 8;       // col offset in tile

    float acc[8][8];
#pragma unroll
    for (int i = 0; i < 8; i++)
#pragma unroll
        for (int j = 0; j < 8; j++) acc[i][j] = 0.f;

    // preload first tile
    {
        float4 av = *(const float4*)Ap;
        float4 bv = *(const float4*)Wp;
        As[0][lk4 + 0][lrow] = av.x; As[0][lk4 + 1][lrow] = av.y;
        As[0][lk4 + 2][lrow] = av.z; As[0][lk4 + 3][lrow] = av.w;
        Bs[0][lk4 + 0][lrow] = bv.x; Bs[0][lk4 + 1][lrow] = bv.y;
        Bs[0][lk4 + 2][lrow] = bv.z; Bs[0][lk4 + 3][lrow] = bv.w;
    }
    __syncthreads();

    int buf = 0;
    for (int kk = 0; kk < K; kk += 8) {
        const bool has_next = (kk + 8) < K;
        float4 anx, bnx;
        if (has_next) {
            anx = *(const float4*)(Ap + kk + 8);
            bnx = *(const float4*)(Wp + kk + 8);
        }

#pragma unroll
        for (int k = 0; k < 8; k++) {
            float a[8], b[8];
            *(float4*)&a[0] = *(const float4*)&As[buf][k][ty8];
            *(float4*)&a[4] = *(const float4*)&As[buf][k][ty8 + 4];
            *(float4*)&b[0] = *(const float4*)&Bs[buf][k][tx8];
            *(float4*)&b[4] = *(const float4*)&Bs[buf][k][tx8 + 4];
#pragma unroll
            for (int i = 0; i < 8; i++)
#pragma unroll
                for (int j = 0; j < 8; j++)
                    acc[i][j] = fmaf(a[i], b[j], acc[i][j]);
        }

        if (has_next) {
            const int nb = buf ^ 1;
            As[nb][lk4 + 0][lrow] = anx.x; As[nb][lk4 + 1][lrow] = anx.y;
            As[nb][lk4 + 2][lrow] = anx.z; As[nb][lk4 + 3][lrow] = anx.w;
            Bs[nb][lk4 + 0][lrow] = bnx.x; Bs[nb][lk4 + 1][lrow] = bnx.y;
            Bs[nb][lk4 + 2][lrow] = bnx.z; Bs[nb][lk4 + 3][lrow] = bnx.w;
        }
        __syncthreads();
        buf ^= 1;
    }

    // epilogue
#pragma unroll
    for (int i = 0; i < 8; i++) {
        const size_t off = (size_t)(r0 + ty8 + i) * ldc + n0 + tx8;
#pragma unroll
        for (int j = 0; j < 8; j++) {
            float v = acc[i][j];
            if (bias)   v += bias[n0 + tx8 + j];
            if (addsrc) v += addsrc[off + j];
            if (act == 1) v = (v > 20.f) ? v : log1pf(__expf(v));
            C[off + j] = v;
        }
    }
}

// ---------------- small NT SGEMM (64x64 tile) for N<128 cases ----------------
__global__ __launch_bounds__(256, 4)
void gemm_nt(const float* __restrict__ A, int lda,
             const float* __restrict__ W, int ldw,
             float* __restrict__ C, int ldc,
             int N, int K,
             const float* __restrict__ bias,
             const float* __restrict__ addsrc,
             int act)
{
    __shared__ float As[64][17];
    __shared__ float Bs[64][17];

    const int tid = threadIdx.x;
    const int r0  = blockIdx.y * 64;
    const int n0  = blockIdx.x * 64;
    const int ty4 = (tid >> 4) * 4;
    const int tx4 = (tid & 15) * 4;

    float acc[4][4];
#pragma unroll
    for (int i = 0; i < 4; i++)
#pragma unroll
        for (int j = 0; j < 4; j++) acc[i][j] = 0.f;

    for (int kk = 0; kk < K; kk += 16) {
#pragma unroll
        for (int p = 0; p < 4; p++) {
            int li  = tid + p * 256;
            int row = li >> 4;
            int col = li & 15;
            As[row][col] = A[(size_t)(r0 + row) * lda + kk + col];
            int nr = n0 + row;
            Bs[row][col] = (nr < N) ? W[(size_t)nr * ldw + kk + col] : 0.f;
        }
        __syncthreads();

#pragma unroll
        for (int k = 0; k < 16; k++) {
            float a0 = As[ty4 + 0][k], a1 = As[ty4 + 1][k];
            float a2 = As[ty4 + 2][k], a3 = As[ty4 + 3][k];
            float b0 = Bs[tx4 + 0][k], b1 = Bs[tx4 + 1][k];
            float b2 = Bs[tx4 + 2][k], b3 = Bs[tx4 + 3][k];
            acc[0][0] = fmaf(a0, b0, acc[0][0]); acc[0][1] = fmaf(a0, b1, acc[0][1]);
            acc[0][2] = fmaf(a0, b2, acc[0][2]); acc[0][3] = fmaf(a0, b3, acc[0][3]);
            acc[1][0] = fmaf(a1, b0, acc[1][0]); acc[1][1] = fmaf(a1, b1, acc[1][1]);
            acc[1][2] = fmaf(a1, b2, acc[1][2]); acc[1][3] = fmaf(a1, b3, acc[1][3]);
            acc[2][0] = fmaf(a2, b0, acc[2][0]); acc[2][1] = fmaf(a2, b1, acc[2][1]);
            acc[2][2] = fmaf(a2, b2, acc[2][2]); acc[2][3] = fmaf(a2, b3, acc[2][3]);
            acc[3][0] = fmaf(a3, b0, acc[3][0]); acc[3][1] = fmaf(a3, b1, acc[3][1]);
            acc[3][2] = fmaf(a3, b2, acc[3][2]); acc[3][3] = fmaf(a3, b3, acc[3][3]);
        }
        __syncthreads();
    }

#pragma unroll
    for (int i = 0; i < 4; i++) {
        int m = r0 + ty4 + i;
#pragma unroll
        for (int j = 0; j < 4; j++) {
            int n = n0 + tx4 + j;
            if (n < N) {
                float v = acc[i][j];
                if (bias)   v += bias[n];
                if (addsrc) v += addsrc[(size_t)m * ldc + n];
                if (act == 1) v = (v > 20.f) ? v : log1pf(__expf(v));
                C[(size_t)m * ldc + n] = v;
            }
        }
    }
}

// ---------------- RMSNorm over last dim (=512), one block per row ----------------
__global__ void rmsnorm_k(const float* __restrict__ x, const float* __restrict__ w,
                          float* __restrict__ o)
{
    const int row = blockIdx.x;
    const int tid = threadIdx.x;
    const float* xr = x + (size_t)row * DMODEL;
    float v0 = xr[tid];
    float v1 = xr[tid + 256];
    float s  = v0 * v0 + v1 * v1;
#pragma unroll
    for (int off = 16; off; off >>= 1) s += __shfl_xor_sync(0xffffffffu, s, off);
    __shared__ float ws[8];
    if ((tid & 31) == 0) ws[tid >> 5] = s;
    __syncthreads();
    if (tid < 32) {
        float t = (tid < 8) ? ws[tid] : 0.f;
#pragma unroll
        for (int off = 4; off; off >>= 1) t += __shfl_xor_sync(0xffffffffu, t, off);
        if (tid == 0) ws[0] = t;
    }
    __syncthreads();
    float scale = rsqrtf(ws[0] * (1.f / DMODEL) + 1e-5f);
    float* orow = o + (size_t)row * DMODEL;
    orow[tid]       = v0 * scale * w[tid];
    orow[tid + 256] = v1 * scale * w[tid + 256];
}

// ---------------- causal depthwise conv (k=4) + bias + silu ----------------
__global__ void conv_silu_k(const float* __restrict__ xr,
                            const float* __restrict__ cw,
                            const float* __restrict__ cb,
                            float* __restrict__ u)
{
    int g = blockIdx.x * blockDim.x + threadIdx.x;
    int d = g & (DINNER - 1);
    int t = (g >> 10) & (LSEQ - 1);
    int b = g >> 20;
    const float* base = xr + ((size_t)(b * LSEQ + t)) * (2 * DINNER) + d;
    float w0 = cw[d * 4 + 0], w1 = cw[d * 4 + 1], w2 = cw[d * 4 + 2], w3 = cw[d * 4 + 3];
    float acc = cb[d] + base[0] * w3;
    if (t >= 1) acc = fmaf(base[-(2 * DINNER)], w2, acc);
    if (t >= 2) acc = fmaf(base[-(4 * DINNER)], w1, acc);
    if (t >= 3) acc = fmaf(base[-(6 * DINNER)], w0, acc);
    u[g] = acc / (1.f + __expf(-acc));
}

// ---------------- selective scan ----------------
__global__ __launch_bounds__(256, 8)
void scan_k(const float* __restrict__ delta, const float* __restrict__ u,
            const float* __restrict__ xdbl,  const float* __restrict__ xr,
            const float* __restrict__ A_log, const float* __restrict__ Dp,
            float* __restrict__ y)
{
    int g  = blockIdx.x * 256 + threadIdx.x;
    int n  = g & 15;
    int bd = g >> 4;
    int d  = bd & (DINNER - 1);
    int b  = bd >> 10;

    const float a  = -__expf(A_log[d * DSTATE + n]);
    const float Dv = Dp[d];

    const float* dp = delta + ((size_t)b * LSEQ) * DINNER + d;
    const float* up = u     + ((size_t)b * LSEQ) * DINNER + d;
    const float* rp = xr    + ((size_t)b * LSEQ) * (2 * DINNER) + DINNER + d;
    const float* xp = xdbl  + ((size_t)b * LSEQ) * 64;
    float*       yp = y     + ((size_t)b * LSEQ) * DINNER + d;

    float h = 0.f;
#pragma unroll 2
    for (int t = 0; t < LSEQ; t++) {
        float dv = dp[(size_t)t << 10];
        float uv = up[(size_t)t << 10];
        float Bv = xp[t * 64 + 32 + n];
        float Cv = xp[t * 64 + 48 + n];
        float dA = __expf(dv * a);
        h = fmaf(dA, h, dv * Bv * uv);
        float p = h * Cv;
        p += __shfl_xor_sync(0xffffffffu, p, 8);
        p += __shfl_xor_sync(0xffffffffu, p, 4);
        p += __shfl_xor_sync(0xffffffffu, p, 2);
        p += __shfl_xor_sync(0xffffffffu, p, 1);
        if (n == 0) {
            float yv = fmaf(uv, Dv, p);
            float r  = rp[(size_t)t << 11];
            yv *= r / (1.f + __expf(-r));
            yp[(size_t)t << 10] = yv;
        }
    }
}

// ---------------- host driver ----------------
extern "C" void kernel_launch(void* const* d_in, const int* in_sizes, int n_in,
                              void* d_out, int out_size)
{
    const float* x        = (const float*)d_in[0];
    const float* in_w     = (const float*)d_in[1];
    const float* in_b     = (const float*)d_in[2];
    const float* norm_w   = (const float*)d_in[3];
    const float* inproj_w = (const float*)d_in[4];
    const float* conv_w   = (const float*)d_in[5];
    const float* conv_b   = (const float*)d_in[6];
    const float* xproj_w  = (const float*)d_in[7];
    const float* dt_w     = (const float*)d_in[8];
    const float* dt_b     = (const float*)d_in[9];
    const float* A_log    = (const float*)d_in[10];
    const float* Dp       = (const float*)d_in[11];
    const float* outproj_w= (const float*)d_in[12];
    const float* normf_w  = (const float*)d_in[13];
    const float* out_w    = (const float*)d_in[14];
    float* out = (float*)d_out;

    float *h, *xn, *xrb, *u, *xdbl, *delta, *y;
    cudaGetSymbolAddress((void**)&h,     g_h);
    cudaGetSymbolAddress((void**)&xn,    g_xn);
    cudaGetSymbolAddress((void**)&xrb,   g_xr);
    cudaGetSymbolAddress((void**)&u,     g_u);
    cudaGetSymbolAddress((void**)&xdbl,  g_xdbl);
    cudaGetSymbolAddress((void**)&delta, g_delta);
    cudaGetSymbolAddress((void**)&y,     g_y);

    const dim3 blk(256);
    const int MB128 = NROWS / 128;   // 32 row-blocks for big gemm
    const int MB64  = NROWS / 64;    // 64 row-blocks for small gemm

    // input projection: h = x @ in_w^T + in_b  (M=4096, N=512, K=80) — big gemm
    gemm_nt_big<<<dim3(DMODEL / 128, MB128), blk>>>(x, NMELS, in_w, NMELS,
                                                    h, DMODEL, NMELS,
                                                    in_b, nullptr, 0);

    for (int i = 0; i < NLAYER; i++) {
        rmsnorm_k<<<NROWS, 256>>>(h, norm_w + (size_t)i * DMODEL, xn);

        // inproj: (4096 x 2048, K=512)
        gemm_nt_big<<<dim3(2 * DINNER / 128, MB128), blk>>>(xn, DMODEL,
            inproj_w + (size_t)i * 2 * DINNER * DMODEL, DMODEL,
            xrb, 2 * DINNER, DMODEL, nullptr, nullptr, 0);

        conv_silu_k<<<(NROWS * DINNER) / 256, 256>>>(xrb,
            conv_w + (size_t)i * DINNER * DCONV, conv_b + (size_t)i * DINNER, u);

        // xproj: (4096 x 64, K=1024) — N too small for big tile
        gemm_nt<<<dim3(1, MB64), blk>>>(u, DINNER,
            xproj_w + (size_t)i * 64 * DINNER, DINNER,
            xdbl, 64, 64, DINNER, nullptr, nullptr, 0);

        // delta = softplus(dt @ dt_w^T + dt_b)  (4096 x 1024, K=32)
        gemm_nt_big<<<dim3(DINNER / 128, MB128), blk>>>(xdbl, 64,
            dt_w + (size_t)i * DINNER * DTRANK, DTRANK,
            delta, DINNER, DTRANK,
            dt_b + (size_t)i * DINNER, nullptr, 1);

        scan_k<<<(NROWS * DSTATE) / 256, 256>>>(delta, u, xdbl, xrb,
            A_log + (size_t)i * DINNER * DSTATE, Dp + (size_t)i * DINNER, y);

        // outproj + residual: (4096 x 512, K=1024)
        gemm_nt_big<<<dim3(DMODEL / 128, MB128), blk>>>(y, DINNER,
            outproj_w + (size_t)i * DMODEL * DINNER, DINNER,
            h, DMODEL, DINNER, nullptr, h, 0);
    }

    rmsnorm_k<<<NROWS, 256>>>(h, normf_w, xn);
    // final: (4096 x 80, K=512) — small gemm (N=80)
    gemm_nt<<<dim3((NMELS + 63) / 64, MB64), blk>>>(xn, DMODEL, out_w, DMODEL,
                                                    out, NMELS, NMELS, DMODEL,
                                                    nullptr, nullptr, 0);
}

// round 12
// speedup vs baseline: 1.1656x; 1.1656x over previous
#include <cuda_runtime.h>
#include <cuda_bf16.h>
#include <math.h>
#include <stdint.h>

// ---------------- problem constants ----------------
#define BATCH   4
#define LSEQ    1024
#define NMELS   80
#define DMODEL  512
#define NLAYER  6
#define DSTATE  16
#define DINNER  1024
#define DTRANK  32
#define DCONV   4
#define NROWS   (BATCH * LSEQ)          // 4096

// ---------------- scratch (static device memory; no allocation) ----------------
__device__ float g_h   [NROWS * DMODEL];
__device__ float g_xn  [NROWS * DMODEL];
__device__ float g_xr  [NROWS * 2 * DINNER];
__device__ float g_u   [NROWS * DINNER];
__device__ float g_xdbl[NROWS * 64];
__device__ float g_delta[NROWS * DINNER];
__device__ float g_y   [NROWS * DINNER];

// ---------------- tf32 helpers ----------------
__device__ __forceinline__ uint32_t f2tf32(float x) {
    uint32_t r;
    asm("cvt.rna.tf32.f32 %0, %1;" : "=r"(r) : "f"(x));
    return r;
}
__device__ __forceinline__ void mma_tf32(float* c, const uint32_t* a, const uint32_t* b) {
    asm volatile(
        "mma.sync.aligned.m16n8k8.row.col.f32.tf32.tf32.f32 "
        "{%0,%1,%2,%3}, {%4,%5,%6,%7}, {%8,%9}, {%0,%1,%2,%3};"
        : "+f"(c[0]), "+f"(c[1]), "+f"(c[2]), "+f"(c[3])
        : "r"(a[0]), "r"(a[1]), "r"(a[2]), "r"(a[3]), "r"(b[0]), "r"(b[1]));
}

// =====================================================================
// TF32 tensor-core NT GEMM: C[m,n] = sum_k A[m,k] * W[n,k]
// Block 128x128, 256 threads (8 warps, 2x4), warp tile 64x32, k-step 16.
// Requires M%128==0, K%16==0. N arbitrary (guarded on B-load + store).
//
// A tile smem: per (kh, 16-row m-slab) slab of 128 floats, BIJECTIVE map
//   P_A(r,c) = 32*(c&3) + 4*((r&7) ^ (2*(c&3))) + 2*(c>>2) + (r>>3)
//   -> A frag for thread (g,t) = one LDS.128 at 32t + 4*(g^(2t)),
//      XOR term makes the 8 lanes of each LDS phase hit distinct bank groups.
// B tile: per (kh, 8-row n-slab) slab of 64 floats
//   P_B(n,c) = 8*(n&7) + 2*(c&3) + (c>>2)
//   -> B frag = one LDS.64 at 8g + 2t (conflict-free).
//
// epilogue: v = acc (+bias[n]) (+addsrc[m*ldc+n]); act==1 -> softplus
// =====================================================================
__global__ __launch_bounds__(256)
void gemm_tf32(const float* __restrict__ A, int lda,
               const float* __restrict__ W, int ldw,
               float* __restrict__ C, int ldc,
               int N, int K,
               const float* __restrict__ bias,
               const float* __restrict__ addsrc,
               int act)
{
    __shared__ __align__(16) float As[2][2048];   // 16 slabs * 128
    __shared__ __align__(16) float Bs[2][2048];   // 32 slabs * 64

    const int tid  = threadIdx.x;
    const int r0   = blockIdx.y * 128;
    const int n0   = blockIdx.x * 128;
    const int lane = tid & 31;
    const int w    = tid >> 5;
    const int g    = lane >> 2;      // group id 0..7
    const int t    = lane & 3;       // thread-in-group 0..3
    const int wm   = w & 1;          // warp row (2 along M)
    const int wn   = w >> 1;         // warp col (4 along N)

    // global staging assignment: row = tid>>1, col-half = (tid&1)*8
    const int lrow = tid >> 1;
    const int lc0  = (tid & 1) * 8;

    const float* Ap   = A + (size_t)(r0 + lrow) * lda + lc0;
    const int    brow = n0 + lrow;
    const bool   bok  = brow < N;
    const float* Wp   = W + (size_t)(bok ? brow : 0) * ldw + lc0;

    // precomputed STS bases for the two float4 halves (c4 = lc0, lc0+4)
    int a_base[2], b_base[2];
    const int rl = lrow & 7;   // r&7 (A) ; also n&7 for B uses nr below
    {
        const int r  = lrow & 15;
        const int ms = lrow >> 4;   // A m-slab (0..7)
        const int nr = lrow & 7;
        const int ns = lrow >> 3;   // B n-slab (0..15)
#pragma unroll
        for (int hh = 0; hh < 2; hh++) {
            const int c4 = lc0 + hh * 4;
            const int kh = c4 >> 3;        // 0/1
            const int cb = c4 & 7;         // 0 or 4
            a_base[hh] = (kh * 8 + ms) * 128 + 2 * (cb >> 2) + (r >> 3);
            b_base[hh] = (kh * 16 + ns) * 64 + 8 * nr + (cb >> 2);
        }
    }

    float acc[4][4][4];
#pragma unroll
    for (int i = 0; i < 4; i++)
#pragma unroll
        for (int j = 0; j < 4; j++)
#pragma unroll
            for (int q = 0; q < 4; q++) acc[i][j][q] = 0.f;

    // A store offsets for components j=0..3: 32*j + 4*(rl ^ (2j))
    const int aj0 = 4 * (rl ^ 0);
    const int aj1 = 32 + 4 * (rl ^ 2);
    const int aj2 = 64 + 4 * (rl ^ 4);
    const int aj3 = 96 + 4 * (rl ^ 6);

#define STAGE(BUF, AV0, AV1, BV0, BV1) do {                                   \
    float* Ad = As[BUF]; float* Bd = Bs[BUF];                                 \
    Ad[a_base[0] + aj0] = __uint_as_float(f2tf32((AV0).x));                   \
    Ad[a_base[0] + aj1] = __uint_as_float(f2tf32((AV0).y));                   \
    Ad[a_base[0] + aj2] = __uint_as_float(f2tf32((AV0).z));                   \
    Ad[a_base[0] + aj3] = __uint_as_float(f2tf32((AV0).w));                   \
    Ad[a_base[1] + aj0] = __uint_as_float(f2tf32((AV1).x));                   \
    Ad[a_base[1] + aj1] = __uint_as_float(f2tf32((AV1).y));                   \
    Ad[a_base[1] + aj2] = __uint_as_float(f2tf32((AV1).z));                   \
    Ad[a_base[1] + aj3] = __uint_as_float(f2tf32((AV1).w));                   \
    Bd[b_base[0] + 0]   = __uint_as_float(f2tf32((BV0).x));                   \
    Bd[b_base[0] + 2]   = __uint_as_float(f2tf32((BV0).y));                   \
    Bd[b_base[0] + 4]   = __uint_as_float(f2tf32((BV0).z));                   \
    Bd[b_base[0] + 6]   = __uint_as_float(f2tf32((BV0).w));                   \
    Bd[b_base[1] + 0]   = __uint_as_float(f2tf32((BV1).x));                   \
    Bd[b_base[1] + 2]   = __uint_as_float(f2tf32((BV1).y));                   \
    Bd[b_base[1] + 4]   = __uint_as_float(f2tf32((BV1).z));                   \
    Bd[b_base[1] + 6]   = __uint_as_float(f2tf32((BV1).w));                   \
} while (0)

    const float4 z4 = make_float4(0.f, 0.f, 0.f, 0.f);

    // prologue: stage first k16 tile
    {
        float4 a0 = *(const float4*)(Ap);
        float4 a1 = *(const float4*)(Ap + 4);
        float4 b0 = bok ? *(const float4*)(Wp)     : z4;
        float4 b1 = bok ? *(const float4*)(Wp + 4) : z4;
        STAGE(0, a0, a1, b0, b1);
    }
    __syncthreads();

    const int a_ld = 32 * t + 4 * (g ^ (2 * t));   // A frag base within slab
    const int b_ld = 8 * g + 2 * t;                // B frag base within slab

    int buf = 0;
    for (int kk = 0; kk < K; kk += 16) {
        const bool nxt = (kk + 16) < K;
        float4 na0, na1, nb0, nb1;
        if (nxt) {
            na0 = *(const float4*)(Ap + kk + 16);
            na1 = *(const float4*)(Ap + kk + 20);
            nb0 = bok ? *(const float4*)(Wp + kk + 16) : z4;
            nb1 = bok ? *(const float4*)(Wp + kk + 20) : z4;
        }

#pragma unroll
        for (int kh = 0; kh < 2; kh++) {
            uint32_t af[4][4], bf[4][2];
#pragma unroll
            for (int mt = 0; mt < 4; mt++) {
                const uint4 v = *(const uint4*)&As[buf][(kh * 8 + wm * 4 + mt) * 128 + a_ld];
                af[mt][0] = v.x; af[mt][1] = v.y; af[mt][2] = v.z; af[mt][3] = v.w;
            }
#pragma unroll
            for (int nt = 0; nt < 4; nt++) {
                const uint2 v = *(const uint2*)&Bs[buf][(kh * 16 + wn * 4 + nt) * 64 + b_ld];
                bf[nt][0] = v.x; bf[nt][1] = v.y;
            }
#pragma unroll
            for (int mt = 0; mt < 4; mt++)
#pragma unroll
                for (int nt = 0; nt < 4; nt++)
                    mma_tf32(acc[mt][nt], af[mt], bf[nt]);
        }

        if (nxt) STAGE(buf ^ 1, na0, na1, nb0, nb1);
        __syncthreads();
        buf ^= 1;
    }
#undef STAGE

    // epilogue (standard m16n8 C ownership: c0/c1 row g, c2/c3 row g+8; cols 2t,2t+1)
#pragma unroll
    for (int mt = 0; mt < 4; mt++) {
        const int rA = r0 + wm * 64 + mt * 16 + g;
        const int rB = rA + 8;
#pragma unroll
        for (int nt = 0; nt < 4; nt++) {
            const int cb = n0 + wn * 32 + nt * 8 + 2 * t;
#pragma unroll
            for (int q = 0; q < 4; q++) {
                const int row = (q < 2) ? rA : rB;
                const int col = cb + (q & 1);
                if (col < N) {
                    float v = acc[mt][nt][q];
                    if (bias)   v += bias[col];
                    if (addsrc) v += addsrc[(size_t)row * ldc + col];
                    if (act == 1) v = (v > 20.f) ? v : log1pf(__expf(v));
                    C[(size_t)row * ldc + col] = v;
                }
            }
        }
    }
}

// ---------------- RMSNorm over last dim (=512), one block per row ----------------
__global__ void rmsnorm_k(const float* __restrict__ x, const float* __restrict__ w,
                          float* __restrict__ o)
{
    const int row = blockIdx.x;
    const int tid = threadIdx.x;
    const float* xr = x + (size_t)row * DMODEL;
    float v0 = xr[tid];
    float v1 = xr[tid + 256];
    float s  = v0 * v0 + v1 * v1;
#pragma unroll
    for (int off = 16; off; off >>= 1) s += __shfl_xor_sync(0xffffffffu, s, off);
    __shared__ float ws[8];
    if ((tid & 31) == 0) ws[tid >> 5] = s;
    __syncthreads();
    if (tid < 32) {
        float tt = (tid < 8) ? ws[tid] : 0.f;
#pragma unroll
        for (int off = 4; off; off >>= 1) tt += __shfl_xor_sync(0xffffffffu, tt, off);
        if (tid == 0) ws[0] = tt;
    }
    __syncthreads();
    float scale = rsqrtf(ws[0] * (1.f / DMODEL) + 1e-5f);
    float* orow = o + (size_t)row * DMODEL;
    orow[tid]       = v0 * scale * w[tid];
    orow[tid + 256] = v1 * scale * w[tid + 256];
}

// ---------------- causal depthwise conv (k=4) + bias + silu ----------------
__global__ void conv_silu_k(const float* __restrict__ xr,
                            const float* __restrict__ cw,
                            const float* __restrict__ cb,
                            float* __restrict__ u)
{
    int gi = blockIdx.x * blockDim.x + threadIdx.x;
    int d = gi & (DINNER - 1);
    int t = (gi >> 10) & (LSEQ - 1);
    int b = gi >> 20;
    const float* base = xr + ((size_t)(b * LSEQ + t)) * (2 * DINNER) + d;
    float w0 = cw[d * 4 + 0], w1 = cw[d * 4 + 1], w2 = cw[d * 4 + 2], w3 = cw[d * 4 + 3];
    float acc = cb[d] + base[0] * w3;
    if (t >= 1) acc = fmaf(base[-(2 * DINNER)], w2, acc);
    if (t >= 2) acc = fmaf(base[-(4 * DINNER)], w1, acc);
    if (t >= 3) acc = fmaf(base[-(6 * DINNER)], w0, acc);
    u[gi] = acc / (1.f + __expf(-acc));
}

// ---------------- selective scan ----------------
__global__ __launch_bounds__(256, 8)
void scan_k(const float* __restrict__ delta, const float* __restrict__ u,
            const float* __restrict__ xdbl,  const float* __restrict__ xr,
            const float* __restrict__ A_log, const float* __restrict__ Dp,
            float* __restrict__ y)
{
    int gi = blockIdx.x * 256 + threadIdx.x;
    int n  = gi & 15;
    int bd = gi >> 4;
    int d  = bd & (DINNER - 1);
    int b  = bd >> 10;

    const float a  = -__expf(A_log[d * DSTATE + n]);
    const float Dv = Dp[d];

    const float* dp = delta + ((size_t)b * LSEQ) * DINNER + d;
    const float* up = u     + ((size_t)b * LSEQ) * DINNER + d;
    const float* rp = xr    + ((size_t)b * LSEQ) * (2 * DINNER) + DINNER + d;
    const float* xp = xdbl  + ((size_t)b * LSEQ) * 64;
    float*       yp = y     + ((size_t)b * LSEQ) * DINNER + d;

    float h = 0.f;
#pragma unroll 2
    for (int t = 0; t < LSEQ; t++) {
        float dv = dp[(size_t)t << 10];
        float uv = up[(size_t)t << 10];
        float Bv = xp[t * 64 + 32 + n];
        float Cv = xp[t * 64 + 48 + n];
        float dA = __expf(dv * a);
        h = fmaf(dA, h, dv * Bv * uv);
        float p = h * Cv;
        p += __shfl_xor_sync(0xffffffffu, p, 8);
        p += __shfl_xor_sync(0xffffffffu, p, 4);
        p += __shfl_xor_sync(0xffffffffu, p, 2);
        p += __shfl_xor_sync(0xffffffffu, p, 1);
        if (n == 0) {
            float yv = fmaf(uv, Dv, p);
            float r  = rp[(size_t)t << 11];
            yv *= r / (1.f + __expf(-r));
            yp[(size_t)t << 10] = yv;
        }
    }
}

// ---------------- host driver ----------------
extern "C" void kernel_launch(void* const* d_in, const int* in_sizes, int n_in,
                              void* d_out, int out_size)
{
    const float* x        = (const float*)d_in[0];
    const float* in_w     = (const float*)d_in[1];
    const float* in_b     = (const float*)d_in[2];
    const float* norm_w   = (const float*)d_in[3];
    const float* inproj_w = (const float*)d_in[4];
    const float* conv_w   = (const float*)d_in[5];
    const float* conv_b   = (const float*)d_in[6];
    const float* xproj_w  = (const float*)d_in[7];
    const float* dt_w     = (const float*)d_in[8];
    const float* dt_b     = (const float*)d_in[9];
    const float* A_log    = (const float*)d_in[10];
    const float* Dp       = (const float*)d_in[11];
    const float* outproj_w= (const float*)d_in[12];
    const float* normf_w  = (const float*)d_in[13];
    const float* out_w    = (const float*)d_in[14];
    float* out = (float*)d_out;

    float *h, *xn, *xrb, *u, *xdbl, *delta, *y;
    cudaGetSymbolAddress((void**)&h,     g_h);
    cudaGetSymbolAddress((void**)&xn,    g_xn);
    cudaGetSymbolAddress((void**)&xrb,   g_xr);
    cudaGetSymbolAddress((void**)&u,     g_u);
    cudaGetSymbolAddress((void**)&xdbl,  g_xdbl);
    cudaGetSymbolAddress((void**)&delta, g_delta);
    cudaGetSymbolAddress((void**)&y,     g_y);

    const dim3 blk(256);
    const int MB = NROWS / 128;   // 32 row-blocks

    // input projection: h = x @ in_w^T + in_b   (N=512, K=80)
    gemm_tf32<<<dim3(DMODEL / 128, MB), blk>>>(x, NMELS, in_w, NMELS,
                                               h, DMODEL, DMODEL, NMELS,
                                               in_b, nullptr, 0);

    for (int i = 0; i < NLAYER; i++) {
        rmsnorm_k<<<NROWS, 256>>>(h, norm_w + (size_t)i * DMODEL, xn);

        // inproj: (N=2048, K=512)
        gemm_tf32<<<dim3(2 * DINNER / 128, MB), blk>>>(xn, DMODEL,
            inproj_w + (size_t)i * 2 * DINNER * DMODEL, DMODEL,
            xrb, 2 * DINNER, 2 * DINNER, DMODEL, nullptr, nullptr, 0);

        conv_silu_k<<<(NROWS * DINNER) / 256, 256>>>(xrb,
            conv_w + (size_t)i * DINNER * DCONV, conv_b + (size_t)i * DINNER, u);

        // xproj: (N=64, K=1024)
        gemm_tf32<<<dim3(1, MB), blk>>>(u, DINNER,
            xproj_w + (size_t)i * 64 * DINNER, DINNER,
            xdbl, 64, 64, DINNER, nullptr, nullptr, 0);

        // delta = softplus(dt @ dt_w^T + dt_b)   (N=1024, K=32)
        gemm_tf32<<<dim3(DINNER / 128, MB), blk>>>(xdbl, 64,
            dt_w + (size_t)i * DINNER * DTRANK, DTRANK,
            delta, DINNER, DINNER, DTRANK,
            dt_b + (size_t)i * DINNER, nullptr, 1);

        scan_k<<<(NROWS * DSTATE) / 256, 256>>>(delta, u, xdbl, xrb,
            A_log + (size_t)i * DINNER * DSTATE, Dp + (size_t)i * DINNER, y);

        // outproj + residual: (N=512, K=1024)
        gemm_tf32<<<dim3(DMODEL / 128, MB), blk>>>(y, DINNER,
            outproj_w + (size_t)i * DMODEL * DINNER, DINNER,
            h, DMODEL, DMODEL, DINNER, nullptr, h, 0);
    }

    rmsnorm_k<<<NROWS, 256>>>(h, normf_w, xn);
    // final: (N=80, K=512)
    gemm_tf32<<<dim3(1, MB), blk>>>(xn, DMODEL, out_w, DMODEL,
                                    out, NMELS, NMELS, DMODEL,
                                    nullptr, nullptr, 0);
}